// round 1
// baseline (speedup 1.0000x reference)
#include <cuda_runtime.h>
#include <cstdint>

#define D 128
#define NMAX 100000
#define EMAX 600000

// ---------------- scratch (static __device__, no allocations) ----------------
__device__ float g_h0[NMAX * D];
__device__ float g_h1[NMAX * D];
__device__ float g_h2[NMAX * D];
__device__ float g_h3[NMAX * D];
__device__ float g_mb[NMAX * D];      // mean agg / pre-cand1
__device__ float g_xb[NMAX * D];      // max agg  / pre-cand2
__device__ float g_y[3L * NMAX * D];  // gemm outputs
__device__ int   g_deg[NMAX];
__device__ int   g_off[NMAX + 1];
__device__ int   g_pos[NMAX];
__device__ int   g_csr[EMAX];
__device__ float g_stats[768];        // [k][sum(128)|sumsq(128)]
__device__ float g_coef[768];         // a[ k*128+d ], then c at +nk*128

// ---------------- small utility kernels ----------------
__global__ void zerof_kernel(float* p, int nel) {
    int i = blockIdx.x * blockDim.x + threadIdx.x;
    if (i < nel) p[i] = 0.f;
}
__global__ void zeroi_kernel(int* p, int nel) {
    int i = blockIdx.x * blockDim.x + threadIdx.x;
    if (i < nel) p[i] = 0;
}
__global__ void copyi_kernel(const int* __restrict__ a, int* __restrict__ b, int nel) {
    int i = blockIdx.x * blockDim.x + threadIdx.x;
    if (i < nel) b[i] = a[i];
}
__global__ void hist_kernel(const int* __restrict__ ed, int* __restrict__ deg, int e) {
    int i = blockIdx.x * blockDim.x + threadIdx.x;
    if (i < e) atomicAdd(&deg[ed[i]], 1);
}
__global__ void scan_kernel(const int* __restrict__ deg, int* __restrict__ off, int n) {
    __shared__ int sm[1024];
    int t = threadIdx.x;
    int chunk = (n + 1023) >> 10;
    int beg = t * chunk;
    int end = min(beg + chunk, n);
    int s = 0;
    for (int i = beg; i < end; i++) s += deg[i];
    sm[t] = s;
    __syncthreads();
    for (int d = 1; d < 1024; d <<= 1) {
        int v = (t >= d) ? sm[t - d] : 0;
        __syncthreads();
        sm[t] += v;
        __syncthreads();
    }
    int pre = (t == 0) ? 0 : sm[t - 1];
    for (int i = beg; i < end; i++) { off[i] = pre; pre += deg[i]; }
    if (t == 1023) off[n] = sm[1023];
}
__global__ void scatter_kernel(const int* __restrict__ es, const int* __restrict__ ed,
                               int* __restrict__ pos, int* __restrict__ csr, int e) {
    int i = blockIdx.x * blockDim.x + threadIdx.x;
    if (i < e) {
        int p = atomicAdd(&pos[ed[i]], 1);
        csr[p] = es[i];
    }
}
__global__ void pre_kernel(const float* __restrict__ a, const float* __restrict__ b,
                           float* __restrict__ c1, float* __restrict__ c2, int tot4) {
    int i = blockIdx.x * blockDim.x + threadIdx.x;
    if (i >= tot4) return;
    float4 va = reinterpret_cast<const float4*>(a)[i];
    float4 vb = reinterpret_cast<const float4*>(b)[i];
    float4 r1, r2;
    r1.x = va.x - vb.x; r1.y = va.y - vb.y; r1.z = va.z - vb.z; r1.w = va.w - vb.w;
    r2.x = va.x * vb.x; r2.y = va.y * vb.y; r2.z = va.z * vb.z; r2.w = va.w * vb.w;
    reinterpret_cast<float4*>(c1)[i] = r1;
    reinterpret_cast<float4*>(c2)[i] = r2;
}

// ---------------- aggregation: warp per node, CSR, register accumulation ----------------
__global__ void agg_kernel(const float* __restrict__ h, const int* __restrict__ off,
                           const int* __restrict__ csr, float* __restrict__ meanb,
                           float* __restrict__ maxb, int n) {
    int wid = (blockIdx.x * blockDim.x + threadIdx.x) >> 5;
    int lane = threadIdx.x & 31;
    if (wid >= n) return;
    int beg = off[wid], end = off[wid + 1];
    float NI = __int_as_float(0xff800000);  // -inf
    float4 s = make_float4(0.f, 0.f, 0.f, 0.f);
    float4 m = make_float4(NI, NI, NI, NI);
    for (int e = beg; e < end; e++) {
        int src = csr[e];
        float4 v = *reinterpret_cast<const float4*>(h + (size_t)src * D + lane * 4);
        s.x += v.x; s.y += v.y; s.z += v.z; s.w += v.w;
        m.x = fmaxf(m.x, v.x); m.y = fmaxf(m.y, v.y);
        m.z = fmaxf(m.z, v.z); m.w = fmaxf(m.w, v.w);
    }
    int deg = end - beg;
    float inv = (deg > 0) ? (1.0f / (float)deg) : 0.f;
    float4 mn = make_float4(s.x * inv, s.y * inv, s.z * inv, s.w * inv);
    float4 mx = (deg > 0) ? m : make_float4(0.f, 0.f, 0.f, 0.f);
    *reinterpret_cast<float4*>(meanb + (size_t)wid * D + lane * 4) = mn;
    *reinterpret_cast<float4*>(maxb + (size_t)wid * D + lane * 4) = mx;
}

// ---------------- GEMM (3 parallel N x 128 x 128) with fused column stats ----------------
__global__ void __launch_bounds__(256) gemm3_kernel(
    const float* __restrict__ x0, const float* __restrict__ x1, const float* __restrict__ x2,
    const float* __restrict__ W, const float* __restrict__ b,
    float* __restrict__ y, float* __restrict__ stats, int n) {
    const int k = blockIdx.y;
    const float* __restrict__ x = (k == 0) ? x0 : ((k == 1) ? x1 : x2);
    const float* __restrict__ Wk = W + k * D * D;
    __shared__ float As[16][128];
    __shared__ float Bs[16][128];
    __shared__ float csum[128], csq[128];
    float acc[8][8];
#pragma unroll
    for (int i = 0; i < 8; i++)
#pragma unroll
        for (int j = 0; j < 8; j++) acc[i][j] = 0.f;

    const int tid = threadIdx.x;
    const int row0 = blockIdx.x * 128;
    const int ty = tid >> 4, tx = tid & 15;

    for (int kt = 0; kt < 128; kt += 16) {
#pragma unroll
        for (int j = 0; j < 2; j++) {
            int i = tid * 2 + j;
            int r = i >> 2;
            int c = (i & 3) * 4;
            int gr = row0 + r;
            float4 v = make_float4(0.f, 0.f, 0.f, 0.f);
            if (gr < n) v = *reinterpret_cast<const float4*>(x + (size_t)gr * D + kt + c);
            As[c + 0][r] = v.x; As[c + 1][r] = v.y; As[c + 2][r] = v.z; As[c + 3][r] = v.w;
        }
#pragma unroll
        for (int j = 0; j < 2; j++) {
            int i = tid * 2 + j;
            int r = i >> 5;
            int c = (i & 31) * 4;
            *reinterpret_cast<float4*>(&Bs[r][c]) =
                *reinterpret_cast<const float4*>(Wk + (size_t)(kt + r) * D + c);
        }
        __syncthreads();
#pragma unroll
        for (int kk = 0; kk < 16; kk++) {
            float a[8], bb[8];
#pragma unroll
            for (int i = 0; i < 8; i++) a[i] = As[kk][ty * 8 + i];
#pragma unroll
            for (int j = 0; j < 8; j++) bb[j] = Bs[kk][tx * 8 + j];
#pragma unroll
            for (int i = 0; i < 8; i++)
#pragma unroll
                for (int j = 0; j < 8; j++) acc[i][j] = fmaf(a[i], bb[j], acc[i][j]);
        }
        __syncthreads();
    }
    if (tid < 128) { csum[tid] = 0.f; csq[tid] = 0.f; }
    __syncthreads();
    float bias[8];
#pragma unroll
    for (int j = 0; j < 8; j++) bias[j] = b[k * D + tx * 8 + j];
    float ps[8], pq[8];
#pragma unroll
    for (int j = 0; j < 8; j++) { ps[j] = 0.f; pq[j] = 0.f; }
    float* yk = y + (size_t)k * n * D;
#pragma unroll
    for (int i = 0; i < 8; i++) {
        int gr = row0 + ty * 8 + i;
        if (gr < n) {
            float v[8];
#pragma unroll
            for (int j = 0; j < 8; j++) {
                v[j] = acc[i][j] + bias[j];
                ps[j] += v[j];
                pq[j] += v[j] * v[j];
            }
            float4* dst = reinterpret_cast<float4*>(yk + (size_t)gr * D + tx * 8);
            dst[0] = make_float4(v[0], v[1], v[2], v[3]);
            dst[1] = make_float4(v[4], v[5], v[6], v[7]);
        }
    }
#pragma unroll
    for (int j = 0; j < 8; j++) {
        atomicAdd(&csum[tx * 8 + j], ps[j]);
        atomicAdd(&csq[tx * 8 + j], pq[j]);
    }
    __syncthreads();
    if (tid < 128) {
        atomicAdd(&stats[k * 256 + tid], csum[tid]);
        atomicAdd(&stats[k * 256 + 128 + tid], csq[tid]);
    }
}

// ---------------- concat GEMM (K = 384 from three sources) ----------------
__global__ void __launch_bounds__(256) gemmcat_kernel(
    const float* __restrict__ x0, const float* __restrict__ x1, const float* __restrict__ x2,
    const float* __restrict__ Wc, const float* __restrict__ bc,
    float* __restrict__ y, float* __restrict__ stats, int n) {
    __shared__ float As[16][128];
    __shared__ float Bs[16][128];
    __shared__ float csum[128], csq[128];
    float acc[8][8];
#pragma unroll
    for (int i = 0; i < 8; i++)
#pragma unroll
        for (int j = 0; j < 8; j++) acc[i][j] = 0.f;

    const int tid = threadIdx.x;
    const int row0 = blockIdx.x * 128;
    const int ty = tid >> 4, tx = tid & 15;

    for (int kt = 0; kt < 384; kt += 16) {
        const float* __restrict__ x = (kt < 128) ? x0 : ((kt < 256) ? x1 : x2);
        const int kl = kt & 127;
#pragma unroll
        for (int j = 0; j < 2; j++) {
            int i = tid * 2 + j;
            int r = i >> 2;
            int c = (i & 3) * 4;
            int gr = row0 + r;
            float4 v = make_float4(0.f, 0.f, 0.f, 0.f);
            if (gr < n) v = *reinterpret_cast<const float4*>(x + (size_t)gr * D + kl + c);
            As[c + 0][r] = v.x; As[c + 1][r] = v.y; As[c + 2][r] = v.z; As[c + 3][r] = v.w;
        }
#pragma unroll
        for (int j = 0; j < 2; j++) {
            int i = tid * 2 + j;
            int r = i >> 5;
            int c = (i & 31) * 4;
            *reinterpret_cast<float4*>(&Bs[r][c]) =
                *reinterpret_cast<const float4*>(Wc + (size_t)(kt + r) * D + c);
        }
        __syncthreads();
#pragma unroll
        for (int kk = 0; kk < 16; kk++) {
            float a[8], bb[8];
#pragma unroll
            for (int i = 0; i < 8; i++) a[i] = As[kk][ty * 8 + i];
#pragma unroll
            for (int j = 0; j < 8; j++) bb[j] = Bs[kk][tx * 8 + j];
#pragma unroll
            for (int i = 0; i < 8; i++)
#pragma unroll
                for (int j = 0; j < 8; j++) acc[i][j] = fmaf(a[i], bb[j], acc[i][j]);
        }
        __syncthreads();
    }
    if (tid < 128) { csum[tid] = 0.f; csq[tid] = 0.f; }
    __syncthreads();
    float bias[8];
#pragma unroll
    for (int j = 0; j < 8; j++) bias[j] = bc[tx * 8 + j];
    float ps[8], pq[8];
#pragma unroll
    for (int j = 0; j < 8; j++) { ps[j] = 0.f; pq[j] = 0.f; }
#pragma unroll
    for (int i = 0; i < 8; i++) {
        int gr = row0 + ty * 8 + i;
        if (gr < n) {
            float v[8];
#pragma unroll
            for (int j = 0; j < 8; j++) {
                v[j] = acc[i][j] + bias[j];
                ps[j] += v[j];
                pq[j] += v[j] * v[j];
            }
            float4* dst = reinterpret_cast<float4*>(y + (size_t)gr * D + tx * 8);
            dst[0] = make_float4(v[0], v[1], v[2], v[3]);
            dst[1] = make_float4(v[4], v[5], v[6], v[7]);
        }
    }
#pragma unroll
    for (int j = 0; j < 8; j++) {
        atomicAdd(&csum[tx * 8 + j], ps[j]);
        atomicAdd(&csq[tx * 8 + j], pq[j]);
    }
    __syncthreads();
    if (tid < 128) {
        atomicAdd(&stats[tid], csum[tid]);
        atomicAdd(&stats[128 + tid], csq[tid]);
    }
}

// ---------------- normalization coefficient computation ----------------
__global__ void finalize_kernel(const float* __restrict__ stats, const float* __restrict__ g,
                                const float* __restrict__ be, float* __restrict__ coef,
                                int nk, float invN) {
    int i = blockIdx.x * 128 + threadIdx.x;
    if (i < nk * 128) {
        int k = i >> 7, d = i & 127;
        float s = stats[k * 256 + d];
        float q = stats[k * 256 + 128 + d];
        float mu = s * invN;
        float var = fmaxf(q * invN - mu * mu, 0.f);
        float a = rsqrtf(var + 1e-5f) * g[i];
        float c = be[i] - mu * a;
        coef[i] = a;
        coef[nk * 128 + i] = c;
    }
}

// ---------------- normalize + relu + weighted combine ----------------
__global__ void combine3_kernel(const float* __restrict__ y, int n,
                                const float* __restrict__ coef, const float* __restrict__ wv,
                                float* __restrict__ out, int accf) {
    __shared__ float sA[384], sC[384], sw[3];
    int t = threadIdx.x;
    for (int i = t; i < 384; i += blockDim.x) { sA[i] = coef[i]; sC[i] = coef[384 + i]; }
    if (t < 3) sw[t] = wv[t];
    __syncthreads();
    int tot4 = n * 32;
    int i = blockIdx.x * blockDim.x + t;
    if (i >= tot4) return;
    int col = (i * 4) & 127;
    size_t stride = (size_t)n * 32;
    const float4* y4 = reinterpret_cast<const float4*>(y);
    float4 a0 = *reinterpret_cast<float4*>(&sA[col]);
    float4 c0 = *reinterpret_cast<float4*>(&sC[col]);
    float4 a1 = *reinterpret_cast<float4*>(&sA[128 + col]);
    float4 c1 = *reinterpret_cast<float4*>(&sC[128 + col]);
    float4 a2 = *reinterpret_cast<float4*>(&sA[256 + col]);
    float4 c2 = *reinterpret_cast<float4*>(&sC[256 + col]);
    float4 y0 = y4[i], y1 = y4[i + stride], y2 = y4[i + 2 * stride];
    float w0 = sw[0], w1 = sw[1], w2 = sw[2];
    float4 r;
    r.x = w0 * fmaxf(fmaf(y0.x, a0.x, c0.x), 0.f) + w1 * fmaxf(fmaf(y1.x, a1.x, c1.x), 0.f) +
          w2 * fmaxf(fmaf(y2.x, a2.x, c2.x), 0.f);
    r.y = w0 * fmaxf(fmaf(y0.y, a0.y, c0.y), 0.f) + w1 * fmaxf(fmaf(y1.y, a1.y, c1.y), 0.f) +
          w2 * fmaxf(fmaf(y2.y, a2.y, c2.y), 0.f);
    r.z = w0 * fmaxf(fmaf(y0.z, a0.z, c0.z), 0.f) + w1 * fmaxf(fmaf(y1.z, a1.z, c1.z), 0.f) +
          w2 * fmaxf(fmaf(y2.z, a2.z, c2.z), 0.f);
    r.w = w0 * fmaxf(fmaf(y0.w, a0.w, c0.w), 0.f) + w1 * fmaxf(fmaf(y1.w, a1.w, c1.w), 0.f) +
          w2 * fmaxf(fmaf(y2.w, a2.w, c2.w), 0.f);
    float4* o4 = reinterpret_cast<float4*>(out);
    if (accf) {
        float4 p = o4[i];
        r.x += p.x; r.y += p.y; r.z += p.z; r.w += p.w;
    }
    o4[i] = r;
}

__global__ void combinecat_kernel(const float* __restrict__ y, int n,
                                  const float* __restrict__ coef, float* __restrict__ out) {
    __shared__ float sA[128], sC[128];
    int t = threadIdx.x;
    if (t < 128) { sA[t] = coef[t]; sC[t] = coef[128 + t]; }
    __syncthreads();
    int tot4 = n * 32;
    int i = blockIdx.x * blockDim.x + t;
    if (i >= tot4) return;
    int col = (i * 4) & 127;
    float4 a = *reinterpret_cast<float4*>(&sA[col]);
    float4 c = *reinterpret_cast<float4*>(&sC[col]);
    float4 v = reinterpret_cast<const float4*>(y)[i];
    float4 r;
    r.x = fmaxf(fmaf(v.x, a.x, c.x), 0.f);
    r.y = fmaxf(fmaf(v.y, a.y, c.y), 0.f);
    r.z = fmaxf(fmaf(v.z, a.z, c.z), 0.f);
    r.w = fmaxf(fmaf(v.w, a.w, c.w), 0.f);
    reinterpret_cast<float4*>(out)[i] = r;
}

// ---------------- host orchestration ----------------
extern "C" void kernel_launch(void* const* d_in, const int* in_sizes, int n_in,
                              void* d_out, int out_size) {
    const float* src_emb = (const float*)d_in[0];
    const float* hr      = (const float*)d_in[1];
    const int*   edge_src = (const int*)d_in[2];
    const int*   edge_dst = (const int*)d_in[3];
    const float* w_zero  = (const float*)d_in[4];
    const float* w_first = (const float*)d_in[5];
    const float* w_mid   = (const float*)d_in[6];
    const float* w_last  = (const float*)d_in[7];
    const float* W_zero  = (const float*)d_in[8];
    const float* b_zero  = (const float*)d_in[9];
    const float* g_zero  = (const float*)d_in[10];
    const float* be_zero = (const float*)d_in[11];
    const float* W_first = (const float*)d_in[12];
    const float* b_first = (const float*)d_in[13];
    const float* g_first = (const float*)d_in[14];
    const float* be_first = (const float*)d_in[15];
    const float* W_mid   = (const float*)d_in[16];
    const float* b_mid   = (const float*)d_in[17];
    const float* g_mid   = (const float*)d_in[18];
    const float* be_mid  = (const float*)d_in[19];
    const float* W_last  = (const float*)d_in[20];
    const float* b_last  = (const float*)d_in[21];
    const float* g_last  = (const float*)d_in[22];
    const float* be_last = (const float*)d_in[23];
    const float* W_cat   = (const float*)d_in[24];
    const float* b_cat   = (const float*)d_in[25];
    const float* g_cat   = (const float*)d_in[26];
    const float* be_cat  = (const float*)d_in[27];

    const int n = in_sizes[0] / D;
    const int e = in_sizes[2];
    float* out = (float*)d_out;

    float *h0, *h1, *h2, *h3, *mb, *xb, *yb, *stats, *coef;
    int *deg, *off, *pos, *csr;
    cudaGetSymbolAddress((void**)&h0, g_h0);
    cudaGetSymbolAddress((void**)&h1, g_h1);
    cudaGetSymbolAddress((void**)&h2, g_h2);
    cudaGetSymbolAddress((void**)&h3, g_h3);
    cudaGetSymbolAddress((void**)&mb, g_mb);
    cudaGetSymbolAddress((void**)&xb, g_xb);
    cudaGetSymbolAddress((void**)&yb, g_y);
    cudaGetSymbolAddress((void**)&stats, g_stats);
    cudaGetSymbolAddress((void**)&coef, g_coef);
    cudaGetSymbolAddress((void**)&deg, g_deg);
    cudaGetSymbolAddress((void**)&off, g_off);
    cudaGetSymbolAddress((void**)&pos, g_pos);
    cudaGetSymbolAddress((void**)&csr, g_csr);

    const int tot4 = n * 32;
    const int ewb = (tot4 + 255) / 256;      // elementwise blocks
    const int gmb = (n + 127) / 128;         // gemm row blocks
    const float invN = 1.0f / (float)n;

    // --- CSR build (once per launch; edges static within a launch) ---
    zeroi_kernel<<<(n + 255) / 256, 256>>>(deg, n);
    hist_kernel<<<(e + 255) / 256, 256>>>(edge_dst, deg, e);
    scan_kernel<<<1, 1024>>>(deg, off, n);
    copyi_kernel<<<(n + 255) / 256, 256>>>(off, pos, n);
    scatter_kernel<<<(e + 255) / 256, 256>>>(edge_src, edge_dst, pos, csr, e);

    // --- mixed helper ---
    auto mixed = [&](const float* x0, const float* x1, const float* x2,
                     const float* W, const float* bb, const float* gg, const float* bbe,
                     const float* wv, float* outp, int accf) {
        zerof_kernel<<<3, 256>>>(stats, 768);
        dim3 grid(gmb, 3);
        gemm3_kernel<<<grid, 256>>>(x0, x1, x2, W, bb, yb, stats, n);
        finalize_kernel<<<3, 128>>>(stats, gg, bbe, coef, 3, invN);
        combine3_kernel<<<ewb, 256>>>(yb, n, coef, wv, outp, accf);
    };
    auto agg = [&](const float* h) {
        agg_kernel<<<ewb, 256>>>(h, off, csr, mb, xb, n);
    };

    // --- zero op: pre-cands = [src_emb, src-hr, src*hr] ---
    pre_kernel<<<ewb, 256>>>(src_emb, hr, mb, xb, tot4);
    mixed(src_emb, mb, xb, W_zero, b_zero, g_zero, be_zero, w_zero, h0, 0);  // h_in -> h0

    // --- s0 and s1 term 1 share agg(h_in) ---
    agg(h0);
    mixed(h0, mb, xb, W_first, b_first, g_first, be_first, w_first, h1, 0);                      // s0 -> h1
    mixed(h0, mb, xb, W_first + 49152, b_first + 384, g_first + 384, be_first + 384,
          w_first + 3, h2, 0);                                                                   // s1 partial -> h2
    // --- s1 term 2 and mid0 share agg(s0) ---
    agg(h1);
    mixed(h1, mb, xb, W_first + 2 * 49152, b_first + 768, g_first + 768, be_first + 768,
          w_first + 6, h2, 1);                                                                   // s1 -> h2
    mixed(h1, mb, xb, W_mid, b_mid, g_mid, be_mid, w_mid, h3, 0);                                // m0 -> h3
    // --- mid1 on s1 ---
    agg(h2);
    mixed(h2, mb, xb, W_mid + 49152, b_mid + 384, g_mid + 384, be_mid + 384, w_mid + 3, h0, 0);  // m1 -> h0
    // --- s_last = last0(m0) + last1(m1) ---
    agg(h3);
    mixed(h3, mb, xb, W_last, b_last, g_last, be_last, w_last, h1, 0);                           // -> h1
    agg(h0);
    mixed(h0, mb, xb, W_last + 49152, b_last + 384, g_last + 384, be_last + 384, w_last + 3,
          h1, 1);                                                                                // s_last -> h1

    // --- concat [m0|m1|s_last] @ W_cat + batchnorm + relu -> out ---
    zerof_kernel<<<2, 256>>>(stats, 512);
    gemmcat_kernel<<<gmb, 256>>>(h3, h0, h1, W_cat, b_cat, yb, stats, n);
    finalize_kernel<<<1, 128>>>(stats, g_cat, be_cat, coef, 1, invN);
    combinecat_kernel<<<ewb, 256>>>(yb, n, coef, out);
}

// round 3
// speedup vs baseline: 1.3264x; 1.3264x over previous
#include <cuda_runtime.h>
#include <cuda_bf16.h>
#include <cstdint>

#define D 128
#define NMAX 100000
#define EMAX 600000

// ---------------- scratch (static __device__, no allocations) ----------------
__device__ float g_h0[NMAX * D];
__device__ float g_h1[NMAX * D];
__device__ float g_h2[NMAX * D];
__device__ float g_h3[NMAX * D];
__device__ float g_mb[NMAX * D];      // mean agg / pre-cand1
__device__ float g_xb[NMAX * D];      // max agg  / pre-cand2
__device__ float g_y[3L * NMAX * D];  // gemm outputs
__device__ int   g_deg[NMAX];
__device__ int   g_off[NMAX + 1];
__device__ int   g_pos[NMAX];
__device__ int   g_csr[EMAX];
__device__ float g_stats[768];        // [k][sum(128)|sumsq(128)]
__device__ float g_coef[768];         // a[k*128+d], then c at +nk*128

// ================= smem / mma helpers =================
__device__ __forceinline__ uint32_t smem_u32(const void* p) {
    uint32_t a;
    asm("{ .reg .u64 t; cvta.to.shared.u64 t, %1; cvt.u32.u64 %0, t; }" : "=r"(a) : "l"(p));
    return a;
}
__device__ __forceinline__ void ldsm4(uint32_t addr, uint32_t* r) {
    asm volatile("ldmatrix.sync.aligned.m8n8.x4.shared.b16 {%0,%1,%2,%3}, [%4];"
                 : "=r"(r[0]), "=r"(r[1]), "=r"(r[2]), "=r"(r[3]) : "r"(addr));
}
__device__ __forceinline__ void mma16816(float* c, const uint32_t* a, uint32_t b0,
                                         uint32_t b1) {
    asm volatile(
        "mma.sync.aligned.m16n8k16.row.col.f32.bf16.bf16.f32 "
        "{%0,%1,%2,%3}, {%4,%5,%6,%7}, {%8,%9}, {%0,%1,%2,%3};"
        : "+f"(c[0]), "+f"(c[1]), "+f"(c[2]), "+f"(c[3])
        : "r"(a[0]), "r"(a[1]), "r"(a[2]), "r"(a[3]), "r"(b0), "r"(b1));
}

// split-convert 8 floats -> 4x uint32 hi bf16 pairs + 4x uint32 lo pairs
__device__ __forceinline__ void split8(const float* f, uint32_t* hi, uint32_t* lo) {
#pragma unroll
    for (int p = 0; p < 4; p++) {
        float a0 = f[2 * p], a1 = f[2 * p + 1];
        __nv_bfloat16 h0 = __float2bfloat16(a0);
        __nv_bfloat16 h1 = __float2bfloat16(a1);
        float r0 = a0 - __bfloat162float(h0);
        float r1 = a1 - __bfloat162float(h1);
        __nv_bfloat16 l0 = __float2bfloat16(r0);
        __nv_bfloat16 l1 = __float2bfloat16(r1);
        hi[p] = (uint32_t)__bfloat16_as_ushort(h0) | ((uint32_t)__bfloat16_as_ushort(h1) << 16);
        lo[p] = (uint32_t)__bfloat16_as_ushort(l0) | ((uint32_t)__bfloat16_as_ushort(l1) << 16);
    }
}

// smem layout: A[128][264 bf16] (hi cols 0-127, lo 128-255, pad 8), B same, then
// bias(512B) csum(512B) csq(512B)
#define LDKB 528               // row stride bytes (264 bf16)
#define ASZ (128 * LDKB)       // 67584
#define SM_B_OFF ASZ
#define SM_BIAS (2 * ASZ)
#define SM_CSUM (2 * ASZ + 512)
#define SM_CSQ (2 * ASZ + 1024)
#define SMEM_BYTES (2 * ASZ + 1536)

// load x tile (fp32 row-major) into A smem as [hi|lo] padded rows
__device__ __forceinline__ void load_A(char* sc, const float* __restrict__ x, int row0,
                                       int n, int t) {
    int row = t & 127, half = t >> 7;
    int gr = row0 + row;
    const float* xr = x + (size_t)gr * D + half * 64;
    char* rbase = sc + row * LDKB;
#pragma unroll
    for (int j = 0; j < 8; j++) {
        float f[8];
        if (gr < n) {
            float4 u = *(const float4*)(xr + j * 8);
            float4 v = *(const float4*)(xr + j * 8 + 4);
            f[0] = u.x; f[1] = u.y; f[2] = u.z; f[3] = u.w;
            f[4] = v.x; f[5] = v.y; f[6] = v.z; f[7] = v.w;
        } else {
#pragma unroll
            for (int p = 0; p < 8; p++) f[p] = 0.f;
        }
        uint32_t hi[4], lo[4];
        split8(f, hi, lo);
        int col = half * 64 + j * 8;
        *(uint4*)(rbase + col * 2) = make_uint4(hi[0], hi[1], hi[2], hi[3]);
        *(uint4*)(rbase + (col + 128) * 2) = make_uint4(lo[0], lo[1], lo[2], lo[3]);
    }
}

// load W (fp32 [d][f] row-major) transposed into B smem rows=f, cols=d, [hi|lo]
__device__ __forceinline__ void load_B(char* sc, const float* __restrict__ Wk, int t) {
    int f = t & 127;
    int d0 = (t >> 7) * 64;
    char* rbase = sc + SM_B_OFF + f * LDKB;
#pragma unroll
    for (int jd = 0; jd < 64; jd += 8) {
        int d = d0 + jd;
        float w[8];
#pragma unroll
        for (int p = 0; p < 8; p++) w[p] = __ldg(&Wk[(size_t)(d + p) * D + f]);
        uint32_t hi[4], lo[4];
        split8(w, hi, lo);
        *(uint4*)(rbase + d * 2) = make_uint4(hi[0], hi[1], hi[2], hi[3]);
        *(uint4*)(rbase + (d + 128) * 2) = make_uint4(lo[0], lo[1], lo[2], lo[3]);
    }
}

// mainloop: 8 k-steps, 3-term split, 48 mma per k-step per warp
__device__ __forceinline__ void mma_pass(uint32_t sA, uint32_t sB, float acc[2][8][4],
                                         int wm, int wn, int lane) {
    uint32_t a_base = sA + (uint32_t)(wm * 32 + (lane & 15)) * LDKB + (uint32_t)(lane >> 4) * 16;
    uint32_t b_base = sB + (uint32_t)(wn * 64 + (lane & 15)) * LDKB + (uint32_t)(lane >> 4) * 16;
#pragma unroll
    for (int ks = 0; ks < 8; ks++) {
        uint32_t kb = (uint32_t)ks * 32;  // k*2 bytes
        uint32_t ah[2][4], al[2][4];
        ldsm4(a_base + kb, ah[0]);
        ldsm4(a_base + 16 * LDKB + kb, ah[1]);
        ldsm4(a_base + 256 + kb, al[0]);
        ldsm4(a_base + 16 * LDKB + 256 + kb, al[1]);
        uint32_t bh[4][4], bl[4][4];
#pragma unroll
        for (int nt2 = 0; nt2 < 4; nt2++) {
            ldsm4(b_base + (uint32_t)nt2 * 16 * LDKB + kb, bh[nt2]);
            ldsm4(b_base + (uint32_t)nt2 * 16 * LDKB + 256 + kb, bl[nt2]);
        }
#pragma unroll
        for (int mt = 0; mt < 2; mt++)
#pragma unroll
            for (int nt = 0; nt < 8; nt++) {
                int nt2 = nt >> 1, p = nt & 1;
                mma16816(acc[mt][nt], ah[mt], bh[nt2][p], bh[nt2][p + 2]);
                mma16816(acc[mt][nt], al[mt], bh[nt2][p], bh[nt2][p + 2]);
                mma16816(acc[mt][nt], ah[mt], bl[nt2][p], bl[nt2][p + 2]);
            }
    }
}

// epilogue: bias, store y, column sum/sumsq via warp shfl + smem atomics
__device__ __forceinline__ void epilogue(float acc[2][8][4], float* __restrict__ y,
                                         const float* sbias, float* csum, float* csq,
                                         int row0, int n, int wm, int wn, int lane) {
    float ps[8][2], pq[8][2];
#pragma unroll
    for (int nt = 0; nt < 8; nt++) {
        ps[nt][0] = 0.f; ps[nt][1] = 0.f; pq[nt][0] = 0.f; pq[nt][1] = 0.f;
    }
    int mrow = row0 + wm * 32 + (lane >> 2);
#pragma unroll
    for (int mt = 0; mt < 2; mt++) {
#pragma unroll
        for (int h = 0; h < 2; h++) {
            int r = mrow + mt * 16 + h * 8;
            bool ok = r < n;
            float* yr = y + (size_t)r * D;
#pragma unroll
            for (int nt = 0; nt < 8; nt++) {
                int col = wn * 64 + nt * 8 + (lane & 3) * 2;
                float c0 = acc[mt][nt][h * 2 + 0] + sbias[col];
                float c1 = acc[mt][nt][h * 2 + 1] + sbias[col + 1];
                if (ok) {
                    *(float2*)(yr + col) = make_float2(c0, c1);
                    ps[nt][0] += c0; ps[nt][1] += c1;
                    pq[nt][0] += c0 * c0; pq[nt][1] += c1 * c1;
                }
            }
        }
    }
    // reduce over lane>>2 groups (lanes with equal lane&3 share columns)
#pragma unroll
    for (int off = 16; off >= 4; off >>= 1) {
#pragma unroll
        for (int nt = 0; nt < 8; nt++) {
            ps[nt][0] += __shfl_xor_sync(0xffffffffu, ps[nt][0], off);
            ps[nt][1] += __shfl_xor_sync(0xffffffffu, ps[nt][1], off);
            pq[nt][0] += __shfl_xor_sync(0xffffffffu, pq[nt][0], off);
            pq[nt][1] += __shfl_xor_sync(0xffffffffu, pq[nt][1], off);
        }
    }
    if ((lane >> 2) == 0) {
#pragma unroll
        for (int nt = 0; nt < 8; nt++) {
            int col = wn * 64 + nt * 8 + (lane & 3) * 2;
            atomicAdd(&csum[col], ps[nt][0]);
            atomicAdd(&csum[col + 1], ps[nt][1]);
            atomicAdd(&csq[col], pq[nt][0]);
            atomicAdd(&csq[col + 1], pq[nt][1]);
        }
    }
}

// ---------------- GEMM (3 parallel N x 128 x 128) with fused column stats ----------------
__global__ void __launch_bounds__(256) gemm3_tc_kernel(
    const float* __restrict__ x0, const float* __restrict__ x1, const float* __restrict__ x2,
    const float* __restrict__ W, const float* __restrict__ b,
    float* __restrict__ y, float* __restrict__ stats, int n) {
    extern __shared__ char sc[];
    uint32_t sbase = smem_u32(sc);
    float* sbias = (float*)(sc + SM_BIAS);
    float* csum = (float*)(sc + SM_CSUM);
    float* csq = (float*)(sc + SM_CSQ);

    const int t = threadIdx.x;
    const int wid = t >> 5, lane = t & 31;
    const int wm = wid & 3, wn = wid >> 2;
    const int kidx = blockIdx.y;
    const float* __restrict__ x = kidx == 0 ? x0 : (kidx == 1 ? x1 : x2);
    const float* __restrict__ Wk = W + (size_t)kidx * D * D;
    const int row0 = blockIdx.x * 128;

    if (t < 128) {
        sbias[t] = b[kidx * D + t];
        csum[t] = 0.f;
        csq[t] = 0.f;
    }
    load_A(sc, x, row0, n, t);
    load_B(sc, Wk, t);
    __syncthreads();

    float acc[2][8][4];
#pragma unroll
    for (int i = 0; i < 2; i++)
#pragma unroll
        for (int j = 0; j < 8; j++)
#pragma unroll
            for (int q = 0; q < 4; q++) acc[i][j][q] = 0.f;

    mma_pass(sbase, sbase + SM_B_OFF, acc, wm, wn, lane);

    epilogue(acc, y + (size_t)kidx * n * D, sbias, csum, csq, row0, n, wm, wn, lane);
    __syncthreads();
    if (t < 128) {
        atomicAdd(&stats[kidx * 256 + t], csum[t]);
        atomicAdd(&stats[kidx * 256 + 128 + t], csq[t]);
    }
}

// ---------------- concat GEMM (K = 3x128 from three sources) ----------------
__global__ void __launch_bounds__(256) gemmcat_tc_kernel(
    const float* __restrict__ x0, const float* __restrict__ x1, const float* __restrict__ x2,
    const float* __restrict__ Wc, const float* __restrict__ bc,
    float* __restrict__ y, float* __restrict__ stats, int n) {
    extern __shared__ char sc[];
    uint32_t sbase = smem_u32(sc);
    float* sbias = (float*)(sc + SM_BIAS);
    float* csum = (float*)(sc + SM_CSUM);
    float* csq = (float*)(sc + SM_CSQ);

    const int t = threadIdx.x;
    const int wid = t >> 5, lane = t & 31;
    const int wm = wid & 3, wn = wid >> 2;
    const int row0 = blockIdx.x * 128;

    if (t < 128) {
        sbias[t] = bc[t];
        csum[t] = 0.f;
        csq[t] = 0.f;
    }

    float acc[2][8][4];
#pragma unroll
    for (int i = 0; i < 2; i++)
#pragma unroll
        for (int j = 0; j < 8; j++)
#pragma unroll
            for (int q = 0; q < 4; q++) acc[i][j][q] = 0.f;

    for (int c = 0; c < 3; c++) {
        if (c) __syncthreads();  // previous mainloop done before overwriting smem
        const float* __restrict__ x = c == 0 ? x0 : (c == 1 ? x1 : x2);
        load_A(sc, x, row0, n, t);
        load_B(sc, Wc + (size_t)c * D * D, t);
        __syncthreads();
        mma_pass(sbase, sbase + SM_B_OFF, acc, wm, wn, lane);
    }

    epilogue(acc, y, sbias, csum, csq, row0, n, wm, wn, lane);
    __syncthreads();
    if (t < 128) {
        atomicAdd(&stats[t], csum[t]);
        atomicAdd(&stats[128 + t], csq[t]);
    }
}

// ---------------- small utility kernels ----------------
__global__ void zerof_kernel(float* p, int nel) {
    int i = blockIdx.x * blockDim.x + threadIdx.x;
    if (i < nel) p[i] = 0.f;
}
__global__ void zeroi_kernel(int* p, int nel) {
    int i = blockIdx.x * blockDim.x + threadIdx.x;
    if (i < nel) p[i] = 0;
}
__global__ void copyi_kernel(const int* __restrict__ a, int* __restrict__ b, int nel) {
    int i = blockIdx.x * blockDim.x + threadIdx.x;
    if (i < nel) b[i] = a[i];
}
__global__ void hist_kernel(const int* __restrict__ ed, int* __restrict__ deg, int e) {
    int i = blockIdx.x * blockDim.x + threadIdx.x;
    if (i < e) atomicAdd(&deg[ed[i]], 1);
}
__global__ void scan_kernel(const int* __restrict__ deg, int* __restrict__ off, int n) {
    __shared__ int sm[1024];
    int t = threadIdx.x;
    int chunk = (n + 1023) >> 10;
    int beg = t * chunk;
    int end = min(beg + chunk, n);
    int s = 0;
    for (int i = beg; i < end; i++) s += deg[i];
    sm[t] = s;
    __syncthreads();
    for (int d = 1; d < 1024; d <<= 1) {
        int v = (t >= d) ? sm[t - d] : 0;
        __syncthreads();
        sm[t] += v;
        __syncthreads();
    }
    int pre = (t == 0) ? 0 : sm[t - 1];
    for (int i = beg; i < end; i++) { off[i] = pre; pre += deg[i]; }
    if (t == 1023) off[n] = sm[1023];
}
__global__ void scatter_kernel(const int* __restrict__ es, const int* __restrict__ ed,
                               int* __restrict__ pos, int* __restrict__ csr, int e) {
    int i = blockIdx.x * blockDim.x + threadIdx.x;
    if (i < e) {
        int p = atomicAdd(&pos[ed[i]], 1);
        csr[p] = es[i];
    }
}
__global__ void pre_kernel(const float* __restrict__ a, const float* __restrict__ b,
                           float* __restrict__ c1, float* __restrict__ c2, int tot4) {
    int i = blockIdx.x * blockDim.x + threadIdx.x;
    if (i >= tot4) return;
    float4 va = reinterpret_cast<const float4*>(a)[i];
    float4 vb = reinterpret_cast<const float4*>(b)[i];
    float4 r1, r2;
    r1.x = va.x - vb.x; r1.y = va.y - vb.y; r1.z = va.z - vb.z; r1.w = va.w - vb.w;
    r2.x = va.x * vb.x; r2.y = va.y * vb.y; r2.z = va.z * vb.z; r2.w = va.w * vb.w;
    reinterpret_cast<float4*>(c1)[i] = r1;
    reinterpret_cast<float4*>(c2)[i] = r2;
}

// ---------------- aggregation: warp per node, CSR, register accumulation ----------------
__global__ void agg_kernel(const float* __restrict__ h, const int* __restrict__ off,
                           const int* __restrict__ csr, float* __restrict__ meanb,
                           float* __restrict__ maxb, int n) {
    int wid = (blockIdx.x * blockDim.x + threadIdx.x) >> 5;
    int lane = threadIdx.x & 31;
    if (wid >= n) return;
    int beg = off[wid], end = off[wid + 1];
    float NI = __int_as_float(0xff800000);
    float4 s = make_float4(0.f, 0.f, 0.f, 0.f);
    float4 m = make_float4(NI, NI, NI, NI);
    for (int e = beg; e < end; e++) {
        int src = csr[e];
        float4 v = *reinterpret_cast<const float4*>(h + (size_t)src * D + lane * 4);
        s.x += v.x; s.y += v.y; s.z += v.z; s.w += v.w;
        m.x = fmaxf(m.x, v.x); m.y = fmaxf(m.y, v.y);
        m.z = fmaxf(m.z, v.z); m.w = fmaxf(m.w, v.w);
    }
    int deg = end - beg;
    float inv = (deg > 0) ? (1.0f / (float)deg) : 0.f;
    float4 mn = make_float4(s.x * inv, s.y * inv, s.z * inv, s.w * inv);
    float4 mx = (deg > 0) ? m : make_float4(0.f, 0.f, 0.f, 0.f);
    *reinterpret_cast<float4*>(meanb + (size_t)wid * D + lane * 4) = mn;
    *reinterpret_cast<float4*>(maxb + (size_t)wid * D + lane * 4) = mx;
}

// ---------------- normalization coefficient computation ----------------
__global__ void finalize_kernel(const float* __restrict__ stats, const float* __restrict__ g,
                                const float* __restrict__ be, float* __restrict__ coef,
                                int nk, float invN) {
    int i = blockIdx.x * 128 + threadIdx.x;
    if (i < nk * 128) {
        int k = i >> 7, d = i & 127;
        float s = stats[k * 256 + d];
        float q = stats[k * 256 + 128 + d];
        float mu = s * invN;
        float var = fmaxf(q * invN - mu * mu, 0.f);
        float a = rsqrtf(var + 1e-5f) * g[i];
        float c = be[i] - mu * a;
        coef[i] = a;
        coef[nk * 128 + i] = c;
    }
}

// ---------------- normalize + relu + weighted combine ----------------
__global__ void combine3_kernel(const float* __restrict__ y, int n,
                                const float* __restrict__ coef, const float* __restrict__ wv,
                                float* __restrict__ out, int accf) {
    __shared__ float sA[384], sC[384], sw[3];
    int t = threadIdx.x;
    for (int i = t; i < 384; i += blockDim.x) { sA[i] = coef[i]; sC[i] = coef[384 + i]; }
    if (t < 3) sw[t] = wv[t];
    __syncthreads();
    int tot4 = n * 32;
    int i = blockIdx.x * blockDim.x + t;
    if (i >= tot4) return;
    int col = (i * 4) & 127;
    size_t stride = (size_t)n * 32;
    const float4* y4 = reinterpret_cast<const float4*>(y);
    float4 a0 = *reinterpret_cast<float4*>(&sA[col]);
    float4 c0 = *reinterpret_cast<float4*>(&sC[col]);
    float4 a1 = *reinterpret_cast<float4*>(&sA[128 + col]);
    float4 c1 = *reinterpret_cast<float4*>(&sC[128 + col]);
    float4 a2 = *reinterpret_cast<float4*>(&sA[256 + col]);
    float4 c2 = *reinterpret_cast<float4*>(&sC[256 + col]);
    float4 y0 = y4[i], y1 = y4[i + stride], y2 = y4[i + 2 * stride];
    float w0 = sw[0], w1 = sw[1], w2 = sw[2];
    float4 r;
    r.x = w0 * fmaxf(fmaf(y0.x, a0.x, c0.x), 0.f) + w1 * fmaxf(fmaf(y1.x, a1.x, c1.x), 0.f) +
          w2 * fmaxf(fmaf(y2.x, a2.x, c2.x), 0.f);
    r.y = w0 * fmaxf(fmaf(y0.y, a0.y, c0.y), 0.f) + w1 * fmaxf(fmaf(y1.y, a1.y, c1.y), 0.f) +
          w2 * fmaxf(fmaf(y2.y, a2.y, c2.y), 0.f);
    r.z = w0 * fmaxf(fmaf(y0.z, a0.z, c0.z), 0.f) + w1 * fmaxf(fmaf(y1.z, a1.z, c1.z), 0.f) +
          w2 * fmaxf(fmaf(y2.z, a2.z, c2.z), 0.f);
    r.w = w0 * fmaxf(fmaf(y0.w, a0.w, c0.w), 0.f) + w1 * fmaxf(fmaf(y1.w, a1.w, c1.w), 0.f) +
          w2 * fmaxf(fmaf(y2.w, a2.w, c2.w), 0.f);
    float4* o4 = reinterpret_cast<float4*>(out);
    if (accf) {
        float4 p = o4[i];
        r.x += p.x; r.y += p.y; r.z += p.z; r.w += p.w;
    }
    o4[i] = r;
}

__global__ void combinecat_kernel(const float* __restrict__ y, int n,
                                  const float* __restrict__ coef, float* __restrict__ out) {
    __shared__ float sA[128], sC[128];
    int t = threadIdx.x;
    if (t < 128) { sA[t] = coef[t]; sC[t] = coef[128 + t]; }
    __syncthreads();
    int tot4 = n * 32;
    int i = blockIdx.x * blockDim.x + t;
    if (i >= tot4) return;
    int col = (i * 4) & 127;
    float4 a = *reinterpret_cast<float4*>(&sA[col]);
    float4 c = *reinterpret_cast<float4*>(&sC[col]);
    float4 v = reinterpret_cast<const float4*>(y)[i];
    float4 r;
    r.x = fmaxf(fmaf(v.x, a.x, c.x), 0.f);
    r.y = fmaxf(fmaf(v.y, a.y, c.y), 0.f);
    r.z = fmaxf(fmaf(v.z, a.z, c.z), 0.f);
    r.w = fmaxf(fmaf(v.w, a.w, c.w), 0.f);
    reinterpret_cast<float4*>(out)[i] = r;
}

// ---------------- host orchestration ----------------
extern "C" void kernel_launch(void* const* d_in, const int* in_sizes, int n_in,
                              void* d_out, int out_size) {
    const float* src_emb = (const float*)d_in[0];
    const float* hr      = (const float*)d_in[1];
    const int*   edge_src = (const int*)d_in[2];
    const int*   edge_dst = (const int*)d_in[3];
    const float* w_zero  = (const float*)d_in[4];
    const float* w_first = (const float*)d_in[5];
    const float* w_mid   = (const float*)d_in[6];
    const float* w_last  = (const float*)d_in[7];
    const float* W_zero  = (const float*)d_in[8];
    const float* b_zero  = (const float*)d_in[9];
    const float* g_zero  = (const float*)d_in[10];
    const float* be_zero = (const float*)d_in[11];
    const float* W_first = (const float*)d_in[12];
    const float* b_first = (const float*)d_in[13];
    const float* g_first = (const float*)d_in[14];
    const float* be_first = (const float*)d_in[15];
    const float* W_mid   = (const float*)d_in[16];
    const float* b_mid   = (const float*)d_in[17];
    const float* g_mid   = (const float*)d_in[18];
    const float* be_mid  = (const float*)d_in[19];
    const float* W_last  = (const float*)d_in[20];
    const float* b_last  = (const float*)d_in[21];
    const float* g_last  = (const float*)d_in[22];
    const float* be_last = (const float*)d_in[23];
    const float* W_cat   = (const float*)d_in[24];
    const float* b_cat   = (const float*)d_in[25];
    const float* g_cat   = (const float*)d_in[26];
    const float* be_cat  = (const float*)d_in[27];

    const int n = in_sizes[0] / D;
    const int e = in_sizes[2];
    float* out = (float*)d_out;

    float *h0, *h1, *h2, *h3, *mb, *xb, *yb, *stats, *coef;
    int *deg, *off, *pos, *csr;
    cudaGetSymbolAddress((void**)&h0, g_h0);
    cudaGetSymbolAddress((void**)&h1, g_h1);
    cudaGetSymbolAddress((void**)&h2, g_h2);
    cudaGetSymbolAddress((void**)&h3, g_h3);
    cudaGetSymbolAddress((void**)&mb, g_mb);
    cudaGetSymbolAddress((void**)&xb, g_xb);
    cudaGetSymbolAddress((void**)&yb, g_y);
    cudaGetSymbolAddress((void**)&stats, g_stats);
    cudaGetSymbolAddress((void**)&coef, g_coef);
    cudaGetSymbolAddress((void**)&deg, g_deg);
    cudaGetSymbolAddress((void**)&off, g_off);
    cudaGetSymbolAddress((void**)&pos, g_pos);
    cudaGetSymbolAddress((void**)&csr, g_csr);

    cudaFuncSetAttribute(gemm3_tc_kernel, cudaFuncAttributeMaxDynamicSharedMemorySize,
                         SMEM_BYTES);
    cudaFuncSetAttribute(gemmcat_tc_kernel, cudaFuncAttributeMaxDynamicSharedMemorySize,
                         SMEM_BYTES);

    const int tot4 = n * 32;
    const int ewb = (tot4 + 255) / 256;
    const int gmb = (n + 127) / 128;
    const float invN = 1.0f / (float)n;

    // --- CSR build ---
    zeroi_kernel<<<(n + 255) / 256, 256>>>(deg, n);
    hist_kernel<<<(e + 255) / 256, 256>>>(edge_dst, deg, e);
    scan_kernel<<<1, 1024>>>(deg, off, n);
    copyi_kernel<<<(n + 255) / 256, 256>>>(off, pos, n);
    scatter_kernel<<<(e + 255) / 256, 256>>>(edge_src, edge_dst, pos, csr, e);

    auto mixed = [&](const float* x0, const float* x1, const float* x2,
                     const float* W, const float* bb, const float* gg, const float* bbe,
                     const float* wv, float* outp, int accf) {
        zerof_kernel<<<3, 256>>>(stats, 768);
        dim3 grid(gmb, 3);
        gemm3_tc_kernel<<<grid, 256, SMEM_BYTES>>>(x0, x1, x2, W, bb, yb, stats, n);
        finalize_kernel<<<3, 128>>>(stats, gg, bbe, coef, 3, invN);
        combine3_kernel<<<ewb, 256>>>(yb, n, coef, wv, outp, accf);
    };
    auto agg = [&](const float* h) {
        agg_kernel<<<ewb, 256>>>(h, off, csr, mb, xb, n);
    };

    // --- zero op ---
    pre_kernel<<<ewb, 256>>>(src_emb, hr, mb, xb, tot4);
    mixed(src_emb, mb, xb, W_zero, b_zero, g_zero, be_zero, w_zero, h0, 0);

    // --- s0 and s1 term 1 share agg(h_in) ---
    agg(h0);
    mixed(h0, mb, xb, W_first, b_first, g_first, be_first, w_first, h1, 0);
    mixed(h0, mb, xb, W_first + 49152, b_first + 384, g_first + 384, be_first + 384,
          w_first + 3, h2, 0);
    agg(h1);
    mixed(h1, mb, xb, W_first + 2 * 49152, b_first + 768, g_first + 768, be_first + 768,
          w_first + 6, h2, 1);
    mixed(h1, mb, xb, W_mid, b_mid, g_mid, be_mid, w_mid, h3, 0);
    agg(h2);
    mixed(h2, mb, xb, W_mid + 49152, b_mid + 384, g_mid + 384, be_mid + 384, w_mid + 3, h0, 0);
    agg(h3);
    mixed(h3, mb, xb, W_last, b_last, g_last, be_last, w_last, h1, 0);
    agg(h0);
    mixed(h0, mb, xb, W_last + 49152, b_last + 384, g_last + 384, be_last + 384, w_last + 3,
          h1, 1);

    // --- concat GEMM + batchnorm + relu -> out ---
    zerof_kernel<<<2, 256>>>(stats, 512);
    gemmcat_tc_kernel<<<gmb, 256, SMEM_BYTES>>>(h3, h0, h1, W_cat, b_cat, yb, stats, n);
    finalize_kernel<<<1, 128>>>(stats, g_cat, be_cat, coef, 1, invN);
    combinecat_kernel<<<ewb, 256>>>(yb, n, coef, out);
}

// round 5
// speedup vs baseline: 1.4383x; 1.0843x over previous
#include <cuda_runtime.h>
#include <cuda_bf16.h>
#include <cstdint>

#define D 128
#define NMAX 100000
#define EMAX 600000

// ---------------- scratch (static __device__, no allocations) ----------------
__device__ float g_h0[NMAX * D];
__device__ float g_h1[NMAX * D];
__device__ float g_h2[NMAX * D];
__device__ float g_h3[NMAX * D];
__device__ float g_y[3L * NMAX * D];  // gemm outputs
// bf16 hi/lo activation buffers: rows of 256 bf16 = [hi(128) | lo(128)]
__device__ __nv_bfloat16 g_sb[NMAX * 256];   // src_emb
__device__ __nv_bfloat16 g_hb0[NMAX * 256];
__device__ __nv_bfloat16 g_hb1[NMAX * 256];
__device__ __nv_bfloat16 g_hb2[NMAX * 256];
__device__ __nv_bfloat16 g_hb3[NMAX * 256];
__device__ __nv_bfloat16 g_mbb[NMAX * 256];  // mean agg / pre-cand1
__device__ __nv_bfloat16 g_xbb[NMAX * 256];  // max agg  / pre-cand2
__device__ __nv_bfloat16 g_wb[27 * 32768];   // 27 transposed weight mats [f][hi d|lo d]
__device__ int   g_deg[NMAX];
__device__ int   g_off[NMAX + 1];
__device__ int   g_pos[NMAX];
__device__ int   g_csr[EMAX];
__device__ float g_stats[768];
__device__ float g_coef[768];

// ================= helpers =================
__device__ __forceinline__ uint32_t smem_u32(const void* p) {
    uint32_t a;
    asm("{ .reg .u64 t; cvta.to.shared.u64 t, %1; cvt.u32.u64 %0, t; }" : "=r"(a) : "l"(p));
    return a;
}
__device__ __forceinline__ void ldsm4(uint32_t addr, uint32_t* r) {
    asm volatile("ldmatrix.sync.aligned.m8n8.x4.shared.b16 {%0,%1,%2,%3}, [%4];"
                 : "=r"(r[0]), "=r"(r[1]), "=r"(r[2]), "=r"(r[3]) : "r"(addr));
}
__device__ __forceinline__ void mma16816(float* c, const uint32_t* a, uint32_t b0,
                                         uint32_t b1) {
    asm volatile(
        "mma.sync.aligned.m16n8k16.row.col.f32.bf16.bf16.f32 "
        "{%0,%1,%2,%3}, {%4,%5,%6,%7}, {%8,%9}, {%0,%1,%2,%3};"
        : "+f"(c[0]), "+f"(c[1]), "+f"(c[2]), "+f"(c[3])
        : "r"(a[0]), "r"(a[1]), "r"(a[2]), "r"(a[3]), "r"(b0), "r"(b1));
}
__device__ __forceinline__ uint32_t b2u(__nv_bfloat162 v) {
    return *reinterpret_cast<uint32_t*>(&v);
}
// split 2 floats -> packed hi bf16x2 + lo bf16x2
__device__ __forceinline__ void split2(float2 p, uint32_t& hi, uint32_t& lo) {
    __nv_bfloat162 h = __float22bfloat162_rn(p);
    float2 hb = __bfloat1622float2(h);
    float2 r = make_float2(p.x - hb.x, p.y - hb.y);
    __nv_bfloat162 l = __float22bfloat162_rn(r);
    hi = b2u(h);
    lo = b2u(l);
}
// write 4 fp32 values as bf16 hi/lo into row-major [hi|lo] buffer
__device__ __forceinline__ void write4(__nv_bfloat16* buf, int row, int col, float4 v) {
    uint32_t h0, l0, h1, l1;
    split2(make_float2(v.x, v.y), h0, l0);
    split2(make_float2(v.z, v.w), h1, l1);
    *reinterpret_cast<uint2*>(buf + (size_t)row * 256 + col) = make_uint2(h0, h1);
    *reinterpret_cast<uint2*>(buf + (size_t)row * 256 + 128 + col) = make_uint2(l0, l1);
}

// smem layout: A[128 rows][512B data + 16B pad], B same, then bias/csum/csq
#define LDKB 528
#define ASZ (128 * LDKB)
#define SM_B_OFF ASZ
#define SM_BIAS (2 * ASZ)
#define SM_CSUM (2 * ASZ + 512)
#define SM_CSQ (2 * ASZ + 1024)
#define SMEM_BYTES (2 * ASZ + 1536)

// coalesced copy of bf16 hi/lo tile into padded smem rows (A side, row guard)
__device__ __forceinline__ void load_Abf(char* sc, const __nv_bfloat16* __restrict__ xb,
                                         int row0, int n, int t) {
#pragma unroll
    for (int j = 0; j < 16; j++) {
        int u = j * 256 + t;          // uint4 index in 128x(32 uint4) tile
        int row = u >> 5, c = u & 31;
        int gr = row0 + row;
        uint4 v = make_uint4(0u, 0u, 0u, 0u);
        if (gr < n) v = *reinterpret_cast<const uint4*>(xb + (size_t)gr * 256 + c * 8);
        *reinterpret_cast<uint4*>(sc + row * LDKB + c * 16) = v;
    }
}
__device__ __forceinline__ void load_Bbf(char* sc, const __nv_bfloat16* __restrict__ wm,
                                         int t) {
#pragma unroll
    for (int j = 0; j < 16; j++) {
        int u = j * 256 + t;
        int row = u >> 5, c = u & 31;
        *reinterpret_cast<uint4*>(sc + SM_B_OFF + row * LDKB + c * 16) =
            *reinterpret_cast<const uint4*>(wm + (size_t)row * 256 + c * 8);
    }
}

// mainloop: 8 k-steps, 3-term split (AhBh + AlBh + AhBl)
__device__ __forceinline__ void mma_pass(uint32_t sA, uint32_t sB, float acc[2][8][4],
                                         int wm, int wn, int lane) {
    uint32_t a_base = sA + (uint32_t)(wm * 32 + (lane & 15)) * LDKB + (uint32_t)(lane >> 4) * 16;
    uint32_t b_base = sB + (uint32_t)(wn * 64 + (lane & 15)) * LDKB + (uint32_t)(lane >> 4) * 16;
#pragma unroll
    for (int ks = 0; ks < 8; ks++) {
        uint32_t kb = (uint32_t)ks * 32;
        uint32_t ah[2][4], al[2][4];
        ldsm4(a_base + kb, ah[0]);
        ldsm4(a_base + 16 * LDKB + kb, ah[1]);
        ldsm4(a_base + 256 + kb, al[0]);
        ldsm4(a_base + 16 * LDKB + 256 + kb, al[1]);
        uint32_t bh[4][4], bl[4][4];
#pragma unroll
        for (int nt2 = 0; nt2 < 4; nt2++) {
            ldsm4(b_base + (uint32_t)nt2 * 16 * LDKB + kb, bh[nt2]);
            ldsm4(b_base + (uint32_t)nt2 * 16 * LDKB + 256 + kb, bl[nt2]);
        }
#pragma unroll
        for (int mt = 0; mt < 2; mt++)
#pragma unroll
            for (int nt = 0; nt < 8; nt++) {
                int nt2 = nt >> 1, p = nt & 1;
                mma16816(acc[mt][nt], ah[mt], bh[nt2][p], bh[nt2][p + 2]);
                mma16816(acc[mt][nt], al[mt], bh[nt2][p], bh[nt2][p + 2]);
                mma16816(acc[mt][nt], ah[mt], bl[nt2][p], bl[nt2][p + 2]);
            }
    }
}

// epilogue: bias, store y, column sum/sumsq via warp shfl + smem atomics
__device__ __forceinline__ void epilogue(float acc[2][8][4], float* __restrict__ y,
                                         const float* sbias, float* csum, float* csq,
                                         int row0, int n, int wm, int wn, int lane) {
    float ps[8][2], pq[8][2];
#pragma unroll
    for (int nt = 0; nt < 8; nt++) {
        ps[nt][0] = 0.f; ps[nt][1] = 0.f; pq[nt][0] = 0.f; pq[nt][1] = 0.f;
    }
    int mrow = row0 + wm * 32 + (lane >> 2);
#pragma unroll
    for (int mt = 0; mt < 2; mt++) {
#pragma unroll
        for (int h = 0; h < 2; h++) {
            int r = mrow + mt * 16 + h * 8;
            bool ok = r < n;
            float* yr = y + (size_t)r * D;
#pragma unroll
            for (int nt = 0; nt < 8; nt++) {
                int col = wn * 64 + nt * 8 + (lane & 3) * 2;
                float c0 = acc[mt][nt][h * 2 + 0] + sbias[col];
                float c1 = acc[mt][nt][h * 2 + 1] + sbias[col + 1];
                if (ok) {
                    *(float2*)(yr + col) = make_float2(c0, c1);
                    ps[nt][0] += c0; ps[nt][1] += c1;
                    pq[nt][0] += c0 * c0; pq[nt][1] += c1 * c1;
                }
            }
        }
    }
#pragma unroll
    for (int off = 16; off >= 4; off >>= 1) {
#pragma unroll
        for (int nt = 0; nt < 8; nt++) {
            ps[nt][0] += __shfl_xor_sync(0xffffffffu, ps[nt][0], off);
            ps[nt][1] += __shfl_xor_sync(0xffffffffu, ps[nt][1], off);
            pq[nt][0] += __shfl_xor_sync(0xffffffffu, pq[nt][0], off);
            pq[nt][1] += __shfl_xor_sync(0xffffffffu, pq[nt][1], off);
        }
    }
    if ((lane >> 2) == 0) {
#pragma unroll
        for (int nt = 0; nt < 8; nt++) {
            int col = wn * 64 + nt * 8 + (lane & 3) * 2;
            atomicAdd(&csum[col], ps[nt][0]);
            atomicAdd(&csum[col + 1], ps[nt][1]);
            atomicAdd(&csq[col], pq[nt][0]);
            atomicAdd(&csq[col + 1], pq[nt][1]);
        }
    }
}

// ---------------- weight pre-conversion: transpose + bf16 hi/lo split ----------------
__global__ void convw_kernel(const float* __restrict__ W, __nv_bfloat16* __restrict__ dst) {
    int bm = blockIdx.x;
    const float* Wk = W + (size_t)bm * 16384;
    __nv_bfloat16* ob = dst + (size_t)bm * 32768;
    int t = threadIdx.x;
    int f = t & 127;
    int d0 = (t >> 7) * 64;
#pragma unroll 4
    for (int jd = 0; jd < 64; jd += 4) {
        int d = d0 + jd;
        float w0 = Wk[(size_t)(d + 0) * D + f];
        float w1 = Wk[(size_t)(d + 1) * D + f];
        float w2 = Wk[(size_t)(d + 2) * D + f];
        float w3 = Wk[(size_t)(d + 3) * D + f];
        uint32_t h0, l0, h1, l1;
        split2(make_float2(w0, w1), h0, l0);
        split2(make_float2(w2, w3), h1, l1);
        *reinterpret_cast<uint2*>(ob + (size_t)f * 256 + d) = make_uint2(h0, h1);
        *reinterpret_cast<uint2*>(ob + (size_t)f * 256 + 128 + d) = make_uint2(l0, l1);
    }
}

// ---------------- GEMM (3 parallel N x 128 x 128) with fused column stats ----------------
__global__ void __launch_bounds__(256) gemm3_tc_kernel(
    const __nv_bfloat16* __restrict__ x0, const __nv_bfloat16* __restrict__ x1,
    const __nv_bfloat16* __restrict__ x2, const __nv_bfloat16* __restrict__ wbase,
    const float* __restrict__ b, float* __restrict__ y, float* __restrict__ stats, int n) {
    extern __shared__ char sc[];
    uint32_t sbase = smem_u32(sc);
    float* sbias = (float*)(sc + SM_BIAS);
    float* csum = (float*)(sc + SM_CSUM);
    float* csq = (float*)(sc + SM_CSQ);

    const int t = threadIdx.x;
    const int wid = t >> 5, lane = t & 31;
    const int wm = wid & 3, wn = wid >> 2;
    const int kidx = blockIdx.y;
    const __nv_bfloat16* __restrict__ x = kidx == 0 ? x0 : (kidx == 1 ? x1 : x2);
    const int row0 = blockIdx.x * 128;

    if (t < 128) {
        sbias[t] = b[kidx * D + t];
        csum[t] = 0.f;
        csq[t] = 0.f;
    }
    load_Abf(sc, x, row0, n, t);
    load_Bbf(sc, wbase + (size_t)kidx * 32768, t);
    __syncthreads();

    float acc[2][8][4];
#pragma unroll
    for (int i = 0; i < 2; i++)
#pragma unroll
        for (int j = 0; j < 8; j++)
#pragma unroll
            for (int q = 0; q < 4; q++) acc[i][j][q] = 0.f;

    mma_pass(sbase, sbase + SM_B_OFF, acc, wm, wn, lane);

    epilogue(acc, y + (size_t)kidx * n * D, sbias, csum, csq, row0, n, wm, wn, lane);
    __syncthreads();
    if (t < 128) {
        atomicAdd(&stats[kidx * 256 + t], csum[t]);
        atomicAdd(&stats[kidx * 256 + 128 + t], csq[t]);
    }
}

// ---------------- concat GEMM (K = 3x128 from three sources) ----------------
__global__ void __launch_bounds__(256) gemmcat_tc_kernel(
    const __nv_bfloat16* __restrict__ x0, const __nv_bfloat16* __restrict__ x1,
    const __nv_bfloat16* __restrict__ x2, const __nv_bfloat16* __restrict__ wbase,
    const float* __restrict__ bc, float* __restrict__ y, float* __restrict__ stats, int n) {
    extern __shared__ char sc[];
    uint32_t sbase = smem_u32(sc);
    float* sbias = (float*)(sc + SM_BIAS);
    float* csum = (float*)(sc + SM_CSUM);
    float* csq = (float*)(sc + SM_CSQ);

    const int t = threadIdx.x;
    const int wid = t >> 5, lane = t & 31;
    const int wm = wid & 3, wn = wid >> 2;
    const int row0 = blockIdx.x * 128;

    if (t < 128) {
        sbias[t] = bc[t];
        csum[t] = 0.f;
        csq[t] = 0.f;
    }

    float acc[2][8][4];
#pragma unroll
    for (int i = 0; i < 2; i++)
#pragma unroll
        for (int j = 0; j < 8; j++)
#pragma unroll
            for (int q = 0; q < 4; q++) acc[i][j][q] = 0.f;

    for (int c = 0; c < 3; c++) {
        if (c) __syncthreads();
        const __nv_bfloat16* __restrict__ x = c == 0 ? x0 : (c == 1 ? x1 : x2);
        load_Abf(sc, x, row0, n, t);
        load_Bbf(sc, wbase + (size_t)c * 32768, t);
        __syncthreads();
        mma_pass(sbase, sbase + SM_B_OFF, acc, wm, wn, lane);
    }

    epilogue(acc, y, sbias, csum, csq, row0, n, wm, wn, lane);
    __syncthreads();
    if (t < 128) {
        atomicAdd(&stats[t], csum[t]);
        atomicAdd(&stats[128 + t], csq[t]);
    }
}

// ---------------- small utility kernels ----------------
__global__ void zerof_kernel(float* p, int nel) {
    int i = blockIdx.x * blockDim.x + threadIdx.x;
    if (i < nel) p[i] = 0.f;
}
__global__ void zeroi_kernel(int* p, int nel) {
    int i = blockIdx.x * blockDim.x + threadIdx.x;
    if (i < nel) p[i] = 0;
}
__global__ void copyi_kernel(const int* __restrict__ a, int* __restrict__ b, int nel) {
    int i = blockIdx.x * blockDim.x + threadIdx.x;
    if (i < nel) b[i] = a[i];
}
__global__ void hist_kernel(const int* __restrict__ ed, int* __restrict__ deg, int e) {
    int i = blockIdx.x * blockDim.x + threadIdx.x;
    if (i < e) atomicAdd(&deg[ed[i]], 1);
}
__global__ void scan_kernel(const int* __restrict__ deg, int* __restrict__ off, int n) {
    __shared__ int sm[1024];
    int t = threadIdx.x;
    int chunk = (n + 1023) >> 10;
    int beg = t * chunk;
    int end = min(beg + chunk, n);
    int s = 0;
    for (int i = beg; i < end; i++) s += deg[i];
    sm[t] = s;
    __syncthreads();
    for (int d = 1; d < 1024; d <<= 1) {
        int v = (t >= d) ? sm[t - d] : 0;
        __syncthreads();
        sm[t] += v;
        __syncthreads();
    }
    int pre = (t == 0) ? 0 : sm[t - 1];
    for (int i = beg; i < end; i++) { off[i] = pre; pre += deg[i]; }
    if (t == 1023) off[n] = sm[1023];
}
__global__ void scatter_kernel(const int* __restrict__ es, const int* __restrict__ ed,
                               int* __restrict__ pos, int* __restrict__ csr, int e) {
    int i = blockIdx.x * blockDim.x + threadIdx.x;
    if (i < e) {
        int p = atomicAdd(&pos[ed[i]], 1);
        csr[p] = es[i];
    }
}
// pre: cand0 = src_emb, cand1 = src - hr, cand2 = src * hr -> bf16 hi/lo buffers
__global__ void pre_kernel(const float* __restrict__ a, const float* __restrict__ b,
                           __nv_bfloat16* __restrict__ sb, __nv_bfloat16* __restrict__ c1,
                           __nv_bfloat16* __restrict__ c2, int tot4) {
    int i = blockIdx.x * blockDim.x + threadIdx.x;
    if (i >= tot4) return;
    int row = i >> 5, col = (i & 31) * 4;
    float4 va = reinterpret_cast<const float4*>(a)[i];
    float4 vb = reinterpret_cast<const float4*>(b)[i];
    write4(sb, row, col, va);
    write4(c1, row, col,
           make_float4(va.x - vb.x, va.y - vb.y, va.z - vb.z, va.w - vb.w));
    write4(c2, row, col,
           make_float4(va.x * vb.x, va.y * vb.y, va.z * vb.z, va.w * vb.w));
}

// ---------------- aggregation: warp per node, CSR, bf16 hi/lo outputs ----------------
__global__ void agg_kernel(const float* __restrict__ h, const int* __restrict__ off,
                           const int* __restrict__ csr, __nv_bfloat16* __restrict__ meanb,
                           __nv_bfloat16* __restrict__ maxb, int n) {
    int wid = (blockIdx.x * blockDim.x + threadIdx.x) >> 5;
    int lane = threadIdx.x & 31;
    if (wid >= n) return;
    int beg = off[wid], end = off[wid + 1];
    float NI = __int_as_float(0xff800000);
    float4 s = make_float4(0.f, 0.f, 0.f, 0.f);
    float4 m = make_float4(NI, NI, NI, NI);
    for (int e = beg; e < end; e++) {
        int src = csr[e];
        float4 v = *reinterpret_cast<const float4*>(h + (size_t)src * D + lane * 4);
        s.x += v.x; s.y += v.y; s.z += v.z; s.w += v.w;
        m.x = fmaxf(m.x, v.x); m.y = fmaxf(m.y, v.y);
        m.z = fmaxf(m.z, v.z); m.w = fmaxf(m.w, v.w);
    }
    int deg = end - beg;
    float inv = (deg > 0) ? (1.0f / (float)deg) : 0.f;
    float4 mn = make_float4(s.x * inv, s.y * inv, s.z * inv, s.w * inv);
    float4 mx = (deg > 0) ? m : make_float4(0.f, 0.f, 0.f, 0.f);
    write4(meanb, wid, lane * 4, mn);
    write4(maxb, wid, lane * 4, mx);
}

// ---------------- normalization coefficient computation ----------------
__global__ void finalize_kernel(const float* __restrict__ stats, const float* __restrict__ g,
                                const float* __restrict__ be, float* __restrict__ coef,
                                int nk, float invN) {
    int i = blockIdx.x * 128 + threadIdx.x;
    if (i < nk * 128) {
        int k = i >> 7, d = i & 127;
        float s = stats[k * 256 + d];
        float q = stats[k * 256 + 128 + d];
        float mu = s * invN;
        float var = fmaxf(q * invN - mu * mu, 0.f);
        float a = rsqrtf(var + 1e-5f) * g[i];
        float c = be[i] - mu * a;
        coef[i] = a;
        coef[nk * 128 + i] = c;
    }
}

// ---------------- normalize + relu + weighted combine (fp32 h + bf16 hi/lo h) ----------
__global__ void combine3_kernel(const float* __restrict__ y, int n,
                                const float* __restrict__ coef, const float* __restrict__ wv,
                                float* __restrict__ out, __nv_bfloat16* __restrict__ hb,
                                int accf) {
    __shared__ float sA[384], sC[384], sw[3];
    int t = threadIdx.x;
    for (int i = t; i < 384; i += blockDim.x) { sA[i] = coef[i]; sC[i] = coef[384 + i]; }
    if (t < 3) sw[t] = wv[t];
    __syncthreads();
    int tot4 = n * 32;
    int i = blockIdx.x * blockDim.x + t;
    if (i >= tot4) return;
    int col = (i * 4) & 127;
    int row = i >> 5;
    size_t stride = (size_t)n * 32;
    const float4* y4 = reinterpret_cast<const float4*>(y);
    float4 a0 = *reinterpret_cast<float4*>(&sA[col]);
    float4 c0 = *reinterpret_cast<float4*>(&sC[col]);
    float4 a1 = *reinterpret_cast<float4*>(&sA[128 + col]);
    float4 c1 = *reinterpret_cast<float4*>(&sC[128 + col]);
    float4 a2 = *reinterpret_cast<float4*>(&sA[256 + col]);
    float4 c2 = *reinterpret_cast<float4*>(&sC[256 + col]);
    float4 y0 = y4[i], y1 = y4[i + stride], y2 = y4[i + 2 * stride];
    float w0 = sw[0], w1 = sw[1], w2 = sw[2];
    float4 r;
    r.x = w0 * fmaxf(fmaf(y0.x, a0.x, c0.x), 0.f) + w1 * fmaxf(fmaf(y1.x, a1.x, c1.x), 0.f) +
          w2 * fmaxf(fmaf(y2.x, a2.x, c2.x), 0.f);
    r.y = w0 * fmaxf(fmaf(y0.y, a0.y, c0.y), 0.f) + w1 * fmaxf(fmaf(y1.y, a1.y, c1.y), 0.f) +
          w2 * fmaxf(fmaf(y2.y, a2.y, c2.y), 0.f);
    r.z = w0 * fmaxf(fmaf(y0.z, a0.z, c0.z), 0.f) + w1 * fmaxf(fmaf(y1.z, a1.z, c1.z), 0.f) +
          w2 * fmaxf(fmaf(y2.z, a2.z, c2.z), 0.f);
    r.w = w0 * fmaxf(fmaf(y0.w, a0.w, c0.w), 0.f) + w1 * fmaxf(fmaf(y1.w, a1.w, c1.w), 0.f) +
          w2 * fmaxf(fmaf(y2.w, a2.w, c2.w), 0.f);
    float4* o4 = reinterpret_cast<float4*>(out);
    if (accf) {
        float4 p = o4[i];
        r.x += p.x; r.y += p.y; r.z += p.z; r.w += p.w;
    }
    o4[i] = r;
    write4(hb, row, col, r);
}

__global__ void combinecat_kernel(const float* __restrict__ y, int n,
                                  const float* __restrict__ coef, float* __restrict__ out) {
    __shared__ float sA[128], sC[128];
    int t = threadIdx.x;
    if (t < 128) { sA[t] = coef[t]; sC[t] = coef[128 + t]; }
    __syncthreads();
    int tot4 = n * 32;
    int i = blockIdx.x * blockDim.x + t;
    if (i >= tot4) return;
    int col = (i * 4) & 127;
    float4 a = *reinterpret_cast<float4*>(&sA[col]);
    float4 c = *reinterpret_cast<float4*>(&sC[col]);
    float4 v = reinterpret_cast<const float4*>(y)[i];
    float4 r;
    r.x = fmaxf(fmaf(v.x, a.x, c.x), 0.f);
    r.y = fmaxf(fmaf(v.y, a.y, c.y), 0.f);
    r.z = fmaxf(fmaf(v.z, a.z, c.z), 0.f);
    r.w = fmaxf(fmaf(v.w, a.w, c.w), 0.f);
    reinterpret_cast<float4*>(out)[i] = r;
}

// ---------------- host orchestration ----------------
extern "C" void kernel_launch(void* const* d_in, const int* in_sizes, int n_in,
                              void* d_out, int out_size) {
    const float* src_emb = (const float*)d_in[0];
    const float* hr      = (const float*)d_in[1];
    const int*   edge_src = (const int*)d_in[2];
    const int*   edge_dst = (const int*)d_in[3];
    const float* w_zero  = (const float*)d_in[4];
    const float* w_first = (const float*)d_in[5];
    const float* w_mid   = (const float*)d_in[6];
    const float* w_last  = (const float*)d_in[7];
    const float* W_zero  = (const float*)d_in[8];
    const float* b_zero  = (const float*)d_in[9];
    const float* g_zero  = (const float*)d_in[10];
    const float* be_zero = (const float*)d_in[11];
    const float* W_first = (const float*)d_in[12];
    const float* b_first = (const float*)d_in[13];
    const float* g_first = (const float*)d_in[14];
    const float* be_first = (const float*)d_in[15];
    const float* W_mid   = (const float*)d_in[16];
    const float* b_mid   = (const float*)d_in[17];
    const float* g_mid   = (const float*)d_in[18];
    const float* be_mid  = (const float*)d_in[19];
    const float* W_last  = (const float*)d_in[20];
    const float* b_last  = (const float*)d_in[21];
    const float* g_last  = (const float*)d_in[22];
    const float* be_last = (const float*)d_in[23];
    const float* W_cat   = (const float*)d_in[24];
    const float* b_cat   = (const float*)d_in[25];
    const float* g_cat   = (const float*)d_in[26];
    const float* be_cat  = (const float*)d_in[27];

    const int n = in_sizes[0] / D;
    const int e = in_sizes[2];
    float* out = (float*)d_out;

    float *h0, *h1, *h2, *h3, *yb, *stats, *coef;
    __nv_bfloat16 *sb, *hb0, *hb1, *hb2, *hb3, *mbb, *xbb, *wb;
    int *deg, *off, *pos, *csr;
    cudaGetSymbolAddress((void**)&h0, g_h0);
    cudaGetSymbolAddress((void**)&h1, g_h1);
    cudaGetSymbolAddress((void**)&h2, g_h2);
    cudaGetSymbolAddress((void**)&h3, g_h3);
    cudaGetSymbolAddress((void**)&yb, g_y);
    cudaGetSymbolAddress((void**)&sb, g_sb);
    cudaGetSymbolAddress((void**)&hb0, g_hb0);
    cudaGetSymbolAddress((void**)&hb1, g_hb1);
    cudaGetSymbolAddress((void**)&hb2, g_hb2);
    cudaGetSymbolAddress((void**)&hb3, g_hb3);
    cudaGetSymbolAddress((void**)&mbb, g_mbb);
    cudaGetSymbolAddress((void**)&xbb, g_xbb);
    cudaGetSymbolAddress((void**)&wb, g_wb);
    cudaGetSymbolAddress((void**)&stats, g_stats);
    cudaGetSymbolAddress((void**)&coef, g_coef);
    cudaGetSymbolAddress((void**)&deg, g_deg);
    cudaGetSymbolAddress((void**)&off, g_off);
    cudaGetSymbolAddress((void**)&pos, g_pos);
    cudaGetSymbolAddress((void**)&csr, g_csr);

    cudaFuncSetAttribute(gemm3_tc_kernel, cudaFuncAttributeMaxDynamicSharedMemorySize,
                         SMEM_BYTES);
    cudaFuncSetAttribute(gemmcat_tc_kernel, cudaFuncAttributeMaxDynamicSharedMemorySize,
                         SMEM_BYTES);

    const int tot4 = n * 32;
    const int ewb = (tot4 + 255) / 256;
    const int gmb = (n + 127) / 128;
    const float invN = 1.0f / (float)n;

    // --- weight pre-conversion (27 matrices) ---
    convw_kernel<<<3, 256>>>(W_zero, wb);
    convw_kernel<<<9, 256>>>(W_first, wb + (size_t)3 * 32768);
    convw_kernel<<<6, 256>>>(W_mid, wb + (size_t)12 * 32768);
    convw_kernel<<<6, 256>>>(W_last, wb + (size_t)18 * 32768);
    convw_kernel<<<3, 256>>>(W_cat, wb + (size_t)24 * 32768);

    // --- CSR build ---
    zeroi_kernel<<<(n + 255) / 256, 256>>>(deg, n);
    hist_kernel<<<(e + 255) / 256, 256>>>(edge_dst, deg, e);
    scan_kernel<<<1, 1024>>>(deg, off, n);
    copyi_kernel<<<(n + 255) / 256, 256>>>(off, pos, n);
    scatter_kernel<<<(e + 255) / 256, 256>>>(edge_src, edge_dst, pos, csr, e);

    auto mixed = [&](const __nv_bfloat16* x0, const __nv_bfloat16* x1,
                     const __nv_bfloat16* x2, int wbidx, const float* bb, const float* gg,
                     const float* bbe, const float* wv, float* outp, __nv_bfloat16* hbout,
                     int accf) {
        zerof_kernel<<<3, 256>>>(stats, 768);
        dim3 grid(gmb, 3);
        gemm3_tc_kernel<<<grid, 256, SMEM_BYTES>>>(x0, x1, x2, wb + (size_t)wbidx * 32768,
                                                   bb, yb, stats, n);
        finalize_kernel<<<3, 128>>>(stats, gg, bbe, coef, 3, invN);
        combine3_kernel<<<ewb, 256>>>(yb, n, coef, wv, outp, hbout, accf);
    };
    auto agg = [&](const float* h) {
        agg_kernel<<<ewb, 256>>>(h, off, csr, mbb, xbb, n);
    };

    // --- zero op ---
    pre_kernel<<<ewb, 256>>>(src_emb, hr, sb, mbb, xbb, tot4);
    mixed(sb, mbb, xbb, 0, b_zero, g_zero, be_zero, w_zero, h0, hb0, 0);

    // --- s0 and s1 term 1 share agg(h_in) ---
    agg(h0);
    mixed(hb0, mbb, xbb, 3, b_first, g_first, be_first, w_first, h1, hb1, 0);
    mixed(hb0, mbb, xbb, 6, b_first + 384, g_first + 384, be_first + 384, w_first + 3, h2,
          hb2, 0);
    agg(h1);
    mixed(hb1, mbb, xbb, 9, b_first + 768, g_first + 768, be_first + 768, w_first + 6, h2,
          hb2, 1);
    mixed(hb1, mbb, xbb, 12, b_mid, g_mid, be_mid, w_mid, h3, hb3, 0);
    agg(h2);
    mixed(hb2, mbb, xbb, 15, b_mid + 384, g_mid + 384, be_mid + 384, w_mid + 3, h0, hb0, 0);
    agg(h3);
    mixed(hb3, mbb, xbb, 18, b_last, g_last, be_last, w_last, h1, hb1, 0);
    agg(h0);
    mixed(hb0, mbb, xbb, 21, b_last + 384, g_last + 384, be_last + 384, w_last + 3, h1, hb1,
          1);

    // --- concat GEMM + batchnorm + relu -> out ---
    zerof_kernel<<<2, 256>>>(stats, 512);
    gemmcat_tc_kernel<<<gmb, 256, SMEM_BYTES>>>(hb3, hb0, hb1, wb + (size_t)24 * 32768,
                                                b_cat, yb, stats, n);
    finalize_kernel<<<1, 128>>>(stats, g_cat, be_cat, coef, 1, invN);
    combinecat_kernel<<<ewb, 256>>>(yb, n, coef, out);
}